// round 14
// baseline (speedup 1.0000x reference)
#include <cuda_runtime.h>
#include <cuda_fp16.h>
#include <cstdint>

// ---------------- problem constants ----------------
#define NNODES   50000
#define NEDGES   800000
#define INSZ     128
#define HID      32
#define H1       8
#define C1       (H1*HID)   // 256
#define OUTD     40
#define BUCKET   64         // max in-degree slots (Poisson(16): P(>=64)*N ~ 2e-13)

// ---------------- scratch (device globals; no allocation allowed) ----------------
__device__ __half g_z1h[(size_t)NNODES*C1];   // layer1 projected features (fp16)
__device__ __half g_h1h[(size_t)NNODES*C1];   // layer1 output / layer2 input (fp16)
__device__ float  g_el1[(size_t)NNODES*H1];
__device__ float  g_er1[(size_t)NNODES*H1];
__device__ __half g_z2h[(size_t)NNODES*OUTD]; // layer2 projected features (fp16)
__device__ float  g_el2[NNODES];
__device__ float  g_er2[NNODES];
// bucket CSR by destination
__device__ int g_cnt[NNODES];
__device__ int g_csrc[(size_t)NNODES*BUCKET];

__device__ __forceinline__ float lrelu(float v) { return fmaxf(v, 0.2f * v); }
__device__ __forceinline__ float eluf (float v) { return v > 0.f ? v : (__expf(v) - 1.f); }

// ================= bucket-CSR build =================
__global__ void zero1_k(int n, int* __restrict__ a) {
    int i = blockIdx.x * blockDim.x + threadIdx.x;
    if (i < n) a[i] = 0;
}
__global__ void scatter_k(int E, const int* __restrict__ src, const int* __restrict__ dst,
                          int* __restrict__ cnt, int* __restrict__ csrc) {
    int e = blockIdx.x * blockDim.x + threadIdx.x;
    if (e >= E) return;
    int d = dst[e];
    int p = atomicAdd(&cnt[d], 1);
    if (p < BUCKET) csrc[(size_t)d * BUCKET + p] = src[e];
}

// ================= fp16 tensor-core GEMM + fused attention epilogue =============
__device__ __forceinline__ void mma_f16(float* d, const uint32_t* a, const uint32_t* b) {
    asm volatile(
        "mma.sync.aligned.m16n8k16.row.col.f32.f16.f16.f32 "
        "{%0,%1,%2,%3}, {%4,%5,%6,%7}, {%8,%9}, {%0,%1,%2,%3};\n"
        : "+f"(d[0]), "+f"(d[1]), "+f"(d[2]), "+f"(d[3])
        : "r"(a[0]), "r"(a[1]), "r"(a[2]), "r"(a[3]), "r"(b[0]), "r"(b[1]));
}

// C[M,N] = A[M,K] @ B[K,N]; A fp32/fp16 row-major, B fp32 row-major,
// C fp32 or fp16. fp16 MMA, fp32 accumulate.
// Fused epilogue: el/er per (row, head) from the fp32 accumulators.
template<int N, int K, int BM, int BN, int BK, int WARPS_M, int WARPS_N, int NT,
         bool A_HALF, bool HALF_OUT, int HEAD_W>
__global__ void h16gemm_k(int M, const void* __restrict__ Av,
                          const float* __restrict__ B, void* __restrict__ Cv,
                          const float* __restrict__ al, const float* __restrict__ ar,
                          float* __restrict__ elo, float* __restrict__ ero) {
    constexpr int WM = BM / WARPS_M;
    constexpr int WN = BN / WARPS_N;
    constexpr int MF = WM / 16;
    constexpr int NF = WN / 8;
    constexpr int AS = BK + 8;
    __shared__ __half As[BM][AS];
    __shared__ __half Bs[BN][AS];

    const int tid  = threadIdx.x;
    const int warp = tid >> 5, lane = tid & 31;
    const int g = lane >> 2, tg = lane & 3;
    const int wm = warp % WARPS_M, wn = warp / WARPS_M;
    const int rowBase = blockIdx.y * BM;
    const int colBase = blockIdx.x * BN;

    float acc[MF][NF][4];
#pragma unroll
    for (int i = 0; i < MF; i++)
#pragma unroll
        for (int j = 0; j < NF; j++)
#pragma unroll
            for (int v = 0; v < 4; v++) acc[i][j][v] = 0.f;

    for (int k0 = 0; k0 < K; k0 += BK) {
        if (A_HALF) {
            const __half* A = (const __half*)Av;
#pragma unroll
            for (int l = tid; l < BM * (BK / 4); l += NT) {
                int r = l / (BK / 4), cq = l % (BK / 4);
                int gr = rowBase + r;
                uint2 v = (gr < M) ? *(const uint2*)(A + (size_t)gr * K + k0 + cq * 4)
                                   : make_uint2(0u, 0u);
                *(uint2*)&As[r][cq * 4] = v;
            }
        } else {
            const float* A = (const float*)Av;
#pragma unroll
            for (int l = tid; l < BM * (BK / 4); l += NT) {
                int r = l / (BK / 4), cq = l % (BK / 4);
                int gr = rowBase + r;
                float4 v = (gr < M) ? *(const float4*)(A + (size_t)gr * K + k0 + cq * 4)
                                    : make_float4(0.f, 0.f, 0.f, 0.f);
                __half2 h0 = __floats2half2_rn(v.x, v.y);
                __half2 h1 = __floats2half2_rn(v.z, v.w);
                *(uint2*)&As[r][cq * 4] = make_uint2(*(uint32_t*)&h0, *(uint32_t*)&h1);
            }
        }
#pragma unroll
        for (int l = tid; l < BK * (BN / 4); l += NT) {
            int r = l / (BN / 4), c4 = l % (BN / 4);
            float4 v = *(const float4*)(B + (size_t)(k0 + r) * N + colBase + c4 * 4);
            Bs[c4 * 4 + 0][r] = __float2half_rn(v.x);
            Bs[c4 * 4 + 1][r] = __float2half_rn(v.y);
            Bs[c4 * 4 + 2][r] = __float2half_rn(v.z);
            Bs[c4 * 4 + 3][r] = __float2half_rn(v.w);
        }
        __syncthreads();

#pragma unroll
        for (int ks = 0; ks < BK; ks += 16) {
            uint32_t af[MF][4];
#pragma unroll
            for (int mf = 0; mf < MF; mf++) {
                int m0 = wm * WM + mf * 16;
                af[mf][0] = *(const uint32_t*)&As[m0 + g    ][ks + 2 * tg];
                af[mf][1] = *(const uint32_t*)&As[m0 + g + 8][ks + 2 * tg];
                af[mf][2] = *(const uint32_t*)&As[m0 + g    ][ks + 2 * tg + 8];
                af[mf][3] = *(const uint32_t*)&As[m0 + g + 8][ks + 2 * tg + 8];
            }
            uint32_t bf[NF][2];
#pragma unroll
            for (int nf = 0; nf < NF; nf++) {
                int n0 = wn * WN + nf * 8;
                bf[nf][0] = *(const uint32_t*)&Bs[n0 + g][ks + 2 * tg];
                bf[nf][1] = *(const uint32_t*)&Bs[n0 + g][ks + 2 * tg + 8];
            }
#pragma unroll
            for (int mf = 0; mf < MF; mf++)
#pragma unroll
                for (int nf = 0; nf < NF; nf++)
                    mma_f16(acc[mf][nf], af[mf], bf[nf]);
        }
        __syncthreads();
    }

    // ---- store C ----
#pragma unroll
    for (int mf = 0; mf < MF; mf++)
#pragma unroll
        for (int nf = 0; nf < NF; nf++) {
            int r0 = rowBase + wm * WM + mf * 16 + g;
            int r1 = r0 + 8;
            int col = colBase + wn * WN + nf * 8 + tg * 2;
            if (HALF_OUT) {
                __half* C = (__half*)Cv;
                if (r0 < M)
                    *(__half2*)&C[(size_t)r0 * N + col] =
                        __floats2half2_rn(acc[mf][nf][0], acc[mf][nf][1]);
                if (r1 < M)
                    *(__half2*)&C[(size_t)r1 * N + col] =
                        __floats2half2_rn(acc[mf][nf][2], acc[mf][nf][3]);
            } else {
                float* C = (float*)Cv;
                if (r0 < M)
                    *(float2*)&C[(size_t)r0 * N + col] =
                        make_float2(acc[mf][nf][0], acc[mf][nf][1]);
                if (r1 < M)
                    *(float2*)&C[(size_t)r1 * N + col] =
                        make_float2(acc[mf][nf][2], acc[mf][nf][3]);
            }
        }

    // ---- fused attention projection ----
    {
        constexpr int NH_W = WN / HEAD_W;
        constexpr int NFH  = HEAD_W / 8;
        constexpr int NHT  = N / HEAD_W;
#pragma unroll
        for (int mf = 0; mf < MF; mf++) {
            int r0 = rowBase + wm * WM + mf * 16 + g;
            int r1 = r0 + 8;
#pragma unroll
            for (int h = 0; h < NH_W; h++) {
                float e0 = 0.f, e1 = 0.f, f0 = 0.f, f1 = 0.f;
#pragma unroll
                for (int q = 0; q < NFH; q++) {
                    int nf = h * NFH + q;
                    int c = colBase + wn * WN + nf * 8 + tg * 2;
                    float a0 = al[c], a1 = al[c + 1];
                    float b0 = ar[c], b1 = ar[c + 1];
                    e0 += acc[mf][nf][0] * a0 + acc[mf][nf][1] * a1;
                    f0 += acc[mf][nf][0] * b0 + acc[mf][nf][1] * b1;
                    e1 += acc[mf][nf][2] * a0 + acc[mf][nf][3] * a1;
                    f1 += acc[mf][nf][2] * b0 + acc[mf][nf][3] * b1;
                }
                e0 += __shfl_xor_sync(0xffffffffu, e0, 1);
                e0 += __shfl_xor_sync(0xffffffffu, e0, 2);
                f0 += __shfl_xor_sync(0xffffffffu, f0, 1);
                f0 += __shfl_xor_sync(0xffffffffu, f0, 2);
                e1 += __shfl_xor_sync(0xffffffffu, e1, 1);
                e1 += __shfl_xor_sync(0xffffffffu, e1, 2);
                f1 += __shfl_xor_sync(0xffffffffu, f1, 1);
                f1 += __shfl_xor_sync(0xffffffffu, f1, 2);
                if (tg == 0) {
                    int head = (colBase + wn * WN) / HEAD_W + h;
                    if (r0 < M) { elo[r0 * NHT + head] = e0; ero[r0 * NHT + head] = f0; }
                    if (r1 < M) { elo[r1 * NHT + head] = e1; ero[r1 * NHT + head] = f1; }
                }
            }
        }
    }
}

// ================= layer-1 aggregate: 2 warps per dst, x8 unroll, HFMA2 ==========
// Warp w of node d covers halves [w*128, w*128+128): 4 halves (uint2) per lane.
// Batched alpha: lane L evaluates head L&7 for edges (L>>3) and (L>>3)+4.
__global__ void agg1_csr_k(int N, const int* __restrict__ cnt, const int* __restrict__ csrc,
                           const float* __restrict__ el, const float* __restrict__ er,
                           const __half* __restrict__ z, const float* __restrict__ b,
                           __half* __restrict__ out) {
    int gw = (blockIdx.x * blockDim.x + threadIdx.x) >> 5;   // global warp
    int d  = gw >> 1;
    int wh = gw & 1;                    // which 128-col half this warp owns
    int lane = threadIdx.x & 31;
    if (d >= N) return;
    int deg = cnt[d]; if (deg > BUCKET) deg = BUCKET;
    const int* row = csrc + (size_t)d * BUCKET;
    const int h8   = lane & 7;          // head this lane evaluates in batched alpha
    const int eidx = lane >> 3;         // edge slot (0..3) this lane evaluates
    const int colb = wh * 128;          // half-row base (in half elements)
    const int hh   = wh * 4 + (lane >> 3);  // head owning this lane's 4 columns
    float erh = er[d * H1 + h8];

    float facc[4];
#pragma unroll
    for (int j = 0; j < 4; j++) facc[j] = 0.f;
    float denh = 0.f;

    const __half2 hz = __floats2half2_rn(0.f, 0.f);
    const __half* zc = z + colb;

    int i = 0;
    for (; i + 7 < deg; i += 8) {
        int4 ea = *(const int4*)&row[i];
        int4 eb = *(const int4*)&row[i + 4];
        int ssa = (eidx == 0) ? ea.x : (eidx == 1) ? ea.y : (eidx == 2) ? ea.z : ea.w;
        int ssb = (eidx == 0) ? eb.x : (eidx == 1) ? eb.y : (eidx == 2) ? eb.z : eb.w;
        float exa = __expf(lrelu(el[ssa * H1 + h8] + erh));
        float exb = __expf(lrelu(el[ssb * H1 + h8] + erh));
        denh += exa + exb;
        __half2 a0 = __float2half2_rn(__shfl_sync(0xffffffffu, exa, hh));
        __half2 a1 = __float2half2_rn(__shfl_sync(0xffffffffu, exa, 8  + hh));
        __half2 a2 = __float2half2_rn(__shfl_sync(0xffffffffu, exa, 16 + hh));
        __half2 a3 = __float2half2_rn(__shfl_sync(0xffffffffu, exa, 24 + hh));
        __half2 a4 = __float2half2_rn(__shfl_sync(0xffffffffu, exb, hh));
        __half2 a5 = __float2half2_rn(__shfl_sync(0xffffffffu, exb, 8  + hh));
        __half2 a6 = __float2half2_rn(__shfl_sync(0xffffffffu, exb, 16 + hh));
        __half2 a7 = __float2half2_rn(__shfl_sync(0xffffffffu, exb, 24 + hh));
        uint2 v0 = ((const uint2*)(zc + (size_t)ea.x * C1))[lane];
        uint2 v1 = ((const uint2*)(zc + (size_t)ea.y * C1))[lane];
        uint2 v2 = ((const uint2*)(zc + (size_t)ea.z * C1))[lane];
        uint2 v3 = ((const uint2*)(zc + (size_t)ea.w * C1))[lane];
        uint2 v4 = ((const uint2*)(zc + (size_t)eb.x * C1))[lane];
        uint2 v5 = ((const uint2*)(zc + (size_t)eb.y * C1))[lane];
        uint2 v6 = ((const uint2*)(zc + (size_t)eb.z * C1))[lane];
        uint2 v7 = ((const uint2*)(zc + (size_t)eb.w * C1))[lane];
        __half2 h0 = hz, h1 = hz;
        h0 = __hfma2(*(__half2*)&v0.x, a0, h0);
        h1 = __hfma2(*(__half2*)&v0.y, a0, h1);
        h0 = __hfma2(*(__half2*)&v1.x, a1, h0);
        h1 = __hfma2(*(__half2*)&v1.y, a1, h1);
        h0 = __hfma2(*(__half2*)&v2.x, a2, h0);
        h1 = __hfma2(*(__half2*)&v2.y, a2, h1);
        h0 = __hfma2(*(__half2*)&v3.x, a3, h0);
        h1 = __hfma2(*(__half2*)&v3.y, a3, h1);
        h0 = __hfma2(*(__half2*)&v4.x, a4, h0);
        h1 = __hfma2(*(__half2*)&v4.y, a4, h1);
        h0 = __hfma2(*(__half2*)&v5.x, a5, h0);
        h1 = __hfma2(*(__half2*)&v5.y, a5, h1);
        h0 = __hfma2(*(__half2*)&v6.x, a6, h0);
        h1 = __hfma2(*(__half2*)&v6.y, a6, h1);
        h0 = __hfma2(*(__half2*)&v7.x, a7, h0);
        h1 = __hfma2(*(__half2*)&v7.y, a7, h1);
        float2 p;
        p = __half22float2(h0); facc[0] += p.x; facc[1] += p.y;
        p = __half22float2(h1); facc[2] += p.x; facc[3] += p.y;
    }
    for (; i < deg; i++) {              // tail: lanes 0-7 evaluate heads
        int s = row[i];
        float ex = 0.f;
        if (lane < H1) {
            ex = __expf(lrelu(el[s * H1 + lane] + erh));
            denh += ex;
        }
        float a = __shfl_sync(0xffffffffu, ex, hh);
        uint2 v = ((const uint2*)(zc + (size_t)s * C1))[lane];
        float2 p;
        p = __half22float2(*(__half2*)&v.x); facc[0] += a*p.x; facc[1] += a*p.y;
        p = __half22float2(*(__half2*)&v.y); facc[2] += a*p.x; facc[3] += a*p.y;
    }
    // fold per-lane partial denominators: after xor 8,16 lane L holds den(head L&7)
    denh += __shfl_xor_sync(0xffffffffu, denh, 8);
    denh += __shfl_xor_sync(0xffffffffu, denh, 16);
    float den = __shfl_sync(0xffffffffu, denh, hh);
    float inv = den > 0.f ? 1.f / den : 0.f;

    int col = colb + lane * 4;
    float4 bv = *(const float4*)(b + col);
    __half2 o0 = __floats2half2_rn(eluf(facc[0]*inv + bv.x), eluf(facc[1]*inv + bv.y));
    __half2 o1 = __floats2half2_rn(eluf(facc[2]*inv + bv.z), eluf(facc[3]*inv + bv.w));
    uint2 ov = make_uint2(*(uint32_t*)&o0, *(uint32_t*)&o1);
    ((uint2*)(out + (size_t)d * C1 + colb))[lane] = ov;
}

// ================= layer-2 aggregate: warp per dst, fp16 z2, 2 edges/warp ========
__global__ void agg2_csr_k(int N, const int* __restrict__ cnt, const int* __restrict__ csrc,
                           const float* __restrict__ el, const float* __restrict__ er,
                           const __half* __restrict__ z, const float* __restrict__ b,
                           float* __restrict__ out) {
    int d = (blockIdx.x * blockDim.x + threadIdx.x) >> 5;
    int lane = threadIdx.x & 31;
    if (d >= N) return;
    int deg = cnt[d]; if (deg > BUCKET) deg = BUCKET;
    const int* row = csrc + (size_t)d * BUCKET;
    int half = lane >> 4, hl = lane & 15;
    float erd = er[d];
    float4 acc = make_float4(0.f, 0.f, 0.f, 0.f);
    float den = 0.f;
    for (int i = half; i < deg; i += 2) {
        int s = row[i];
        float ex = __expf(lrelu(el[s] + erd));
        den += ex;
        if (hl < OUTD / 4) {
            uint2 v = ((const uint2*)(z + (size_t)s * OUTD))[hl];
            float2 p0 = __half22float2(*(__half2*)&v.x);
            float2 p1 = __half22float2(*(__half2*)&v.y);
            acc.x += ex * p0.x; acc.y += ex * p0.y;
            acc.z += ex * p1.x; acc.w += ex * p1.y;
        }
    }
    acc.x += __shfl_down_sync(0xffffffffu, acc.x, 16);
    acc.y += __shfl_down_sync(0xffffffffu, acc.y, 16);
    acc.z += __shfl_down_sync(0xffffffffu, acc.z, 16);
    acc.w += __shfl_down_sync(0xffffffffu, acc.w, 16);
    den   += __shfl_down_sync(0xffffffffu, den, 16);
    float inv = den > 0.f ? 1.f / den : 0.f;
    if (lane < OUTD / 4) {
        float4 bv = ((const float4*)b)[lane];
        float4 o;
        o.x = acc.x * inv + bv.x; o.y = acc.y * inv + bv.y;
        o.z = acc.z * inv + bv.z; o.w = acc.w * inv + bv.w;
        ((float4*)(out + (size_t)d * OUTD))[lane] = o;
    }
}

// ---------------- stream/event resources (static-init; serial fallback) ----------
struct SideStream {
    cudaStream_t s = nullptr;
    cudaEvent_t  fork = nullptr, join = nullptr;
    bool ok = false;
    SideStream() {
        ok = (cudaStreamCreateWithFlags(&s, cudaStreamNonBlocking) == cudaSuccess)
          && (cudaEventCreateWithFlags(&fork, cudaEventDisableTiming) == cudaSuccess)
          && (cudaEventCreateWithFlags(&join, cudaEventDisableTiming) == cudaSuccess);
    }
};
static SideStream g_ss;

// ---------------- launch ----------------
static inline int cdiv(int a, int b) { return (a + b - 1) / b; }

extern "C" void kernel_launch(void* const* d_in, const int* in_sizes, int n_in,
                              void* d_out, int out_size) {
    const float* feat = (const float*)d_in[0];
    const int*   src  = (const int*)  d_in[1];
    const int*   dst  = (const int*)  d_in[2];
    const float* W1   = (const float*)d_in[3];
    const float* al1  = (const float*)d_in[4];
    const float* ar1  = (const float*)d_in[5];
    const float* b1   = (const float*)d_in[6];
    const float* W2   = (const float*)d_in[7];
    const float* al2  = (const float*)d_in[8];
    const float* ar2  = (const float*)d_in[9];
    const float* b2   = (const float*)d_in[10];
    float* out = (float*)d_out;

    const int N = in_sizes[0] / INSZ;
    const int E = in_sizes[1];

    __half *z1h, *h1h, *z2h;
    float *el1, *er1, *el2, *er2;
    int *cnt, *csrc;
    cudaGetSymbolAddress((void**)&z1h,  g_z1h);
    cudaGetSymbolAddress((void**)&h1h,  g_h1h);
    cudaGetSymbolAddress((void**)&el1,  g_el1);
    cudaGetSymbolAddress((void**)&er1,  g_er1);
    cudaGetSymbolAddress((void**)&z2h,  g_z2h);
    cudaGetSymbolAddress((void**)&el2,  g_el2);
    cudaGetSymbolAddress((void**)&er2,  g_er2);
    cudaGetSymbolAddress((void**)&cnt,  g_cnt);
    cudaGetSymbolAddress((void**)&csrc, g_csrc);

    const int T = 256;
    const int TA = 128;
    const bool forked = g_ss.ok;
    cudaStream_t sc = forked ? g_ss.s : (cudaStream_t)0;

    if (forked) {
        cudaEventRecord(g_ss.fork, 0);
        cudaStreamWaitEvent(sc, g_ss.fork, 0);
    }

    // ---- bucket-CSR build (side stream; shared by both layers) ----
    zero1_k  <<<cdiv(N, T), T, 0, sc>>>(N, cnt);
    scatter_k<<<cdiv(E, T), T, 0, sc>>>(E, src, dst, cnt, csrc);
    if (forked) cudaEventRecord(g_ss.join, sc);

    // ---- layer 1: GEMM + fused attn projection ----
    {
        dim3 grid(C1 / 128, cdiv(N, 128));
        h16gemm_k<C1, INSZ, 128, 128, 32, 4, 2, 256, false, true, HID>
            <<<grid, 256>>>(N, (const void*)feat, W1, (void*)z1h, al1, ar1, el1, er1);
    }

    if (forked) cudaStreamWaitEvent(0, g_ss.join, 0);

    agg1_csr_k<<<cdiv(N * 64, TA), TA>>>(N, cnt, csrc, el1, er1, z1h, b1, h1h);

    // ---- layer 2: GEMM + fused attn projection ----
    {
        dim3 grid(1, cdiv(N, 128));
        h16gemm_k<OUTD, C1, 128, 40, 32, 4, 1, 128, true, true, OUTD>
            <<<grid, 128>>>(N, (const void*)h1h, W2, (void*)z2h, al2, ar2, el2, er2);
    }
    agg2_csr_k<<<cdiv(N * 32, TA), TA>>>(N, cnt, csrc, el2, er2, z2h, b2, out);
}

// round 16
// speedup vs baseline: 1.1374x; 1.1374x over previous
#include <cuda_runtime.h>
#include <cuda_fp16.h>
#include <cstdint>

// ---------------- problem constants ----------------
#define NNODES   50000
#define NEDGES   800000
#define INSZ     128
#define HID      32
#define H1       8
#define C1       (H1*HID)   // 256
#define OUTD     40
#define BUCKET   64         // max in-degree slots (Poisson(16): P(>=64)*N ~ 2e-13)

// ---------------- scratch (device globals; no allocation allowed) ----------------
__device__ __half g_z1h[(size_t)NNODES*C1];   // layer1 projected features (fp16)
__device__ __half g_h1h[(size_t)NNODES*C1];   // layer1 output / layer2 input (fp16)
__device__ float  g_el1[(size_t)NNODES*H1];
__device__ float  g_er1[(size_t)NNODES*H1];
__device__ __half g_z2h[(size_t)NNODES*OUTD]; // layer2 projected features (fp16)
__device__ float  g_el2[NNODES];
__device__ float  g_er2[NNODES];
// bucket CSR by destination
__device__ int g_cnt[NNODES];
__device__ int g_csrc[(size_t)NNODES*BUCKET];

__device__ __forceinline__ float lrelu(float v) { return fmaxf(v, 0.2f * v); }
__device__ __forceinline__ float eluf (float v) { return v > 0.f ? v : (__expf(v) - 1.f); }

// ================= bucket-CSR build =================
__global__ void zero1_k(int n, int* __restrict__ a) {
    int i = blockIdx.x * blockDim.x + threadIdx.x;
    if (i < n) a[i] = 0;
}
__global__ void scatter_k(int E, const int* __restrict__ src, const int* __restrict__ dst,
                          int* __restrict__ cnt, int* __restrict__ csrc) {
    int e = blockIdx.x * blockDim.x + threadIdx.x;
    if (e >= E) return;
    int d = dst[e];
    int p = atomicAdd(&cnt[d], 1);
    if (p < BUCKET) csrc[(size_t)d * BUCKET + p] = src[e];
}

// ================= fp16 tensor-core GEMM + fused attention epilogue =============
__device__ __forceinline__ void mma_f16(float* d, const uint32_t* a, const uint32_t* b) {
    asm volatile(
        "mma.sync.aligned.m16n8k16.row.col.f32.f16.f16.f32 "
        "{%0,%1,%2,%3}, {%4,%5,%6,%7}, {%8,%9}, {%0,%1,%2,%3};\n"
        : "+f"(d[0]), "+f"(d[1]), "+f"(d[2]), "+f"(d[3])
        : "r"(a[0]), "r"(a[1]), "r"(a[2]), "r"(a[3]), "r"(b[0]), "r"(b[1]));
}

// C[M,N] = A[M,K] @ B[K,N]; A fp32/fp16 row-major, B fp32 row-major,
// C fp32 or fp16. fp16 MMA, fp32 accumulate.
// Fused epilogue: el/er per (row, head) from the fp32 accumulators.
template<int N, int K, int BM, int BN, int BK, int WARPS_M, int WARPS_N, int NT,
         bool A_HALF, bool HALF_OUT, int HEAD_W>
__global__ void h16gemm_k(int M, const void* __restrict__ Av,
                          const float* __restrict__ B, void* __restrict__ Cv,
                          const float* __restrict__ al, const float* __restrict__ ar,
                          float* __restrict__ elo, float* __restrict__ ero) {
    constexpr int WM = BM / WARPS_M;
    constexpr int WN = BN / WARPS_N;
    constexpr int MF = WM / 16;
    constexpr int NF = WN / 8;
    constexpr int AS = BK + 8;
    __shared__ __half As[BM][AS];
    __shared__ __half Bs[BN][AS];

    const int tid  = threadIdx.x;
    const int warp = tid >> 5, lane = tid & 31;
    const int g = lane >> 2, tg = lane & 3;
    const int wm = warp % WARPS_M, wn = warp / WARPS_M;
    const int rowBase = blockIdx.y * BM;
    const int colBase = blockIdx.x * BN;

    float acc[MF][NF][4];
#pragma unroll
    for (int i = 0; i < MF; i++)
#pragma unroll
        for (int j = 0; j < NF; j++)
#pragma unroll
            for (int v = 0; v < 4; v++) acc[i][j][v] = 0.f;

    for (int k0 = 0; k0 < K; k0 += BK) {
        if (A_HALF) {
            const __half* A = (const __half*)Av;
#pragma unroll
            for (int l = tid; l < BM * (BK / 4); l += NT) {
                int r = l / (BK / 4), cq = l % (BK / 4);
                int gr = rowBase + r;
                uint2 v = (gr < M) ? *(const uint2*)(A + (size_t)gr * K + k0 + cq * 4)
                                   : make_uint2(0u, 0u);
                *(uint2*)&As[r][cq * 4] = v;
            }
        } else {
            const float* A = (const float*)Av;
#pragma unroll
            for (int l = tid; l < BM * (BK / 4); l += NT) {
                int r = l / (BK / 4), cq = l % (BK / 4);
                int gr = rowBase + r;
                float4 v = (gr < M) ? *(const float4*)(A + (size_t)gr * K + k0 + cq * 4)
                                    : make_float4(0.f, 0.f, 0.f, 0.f);
                __half2 h0 = __floats2half2_rn(v.x, v.y);
                __half2 h1 = __floats2half2_rn(v.z, v.w);
                *(uint2*)&As[r][cq * 4] = make_uint2(*(uint32_t*)&h0, *(uint32_t*)&h1);
            }
        }
#pragma unroll
        for (int l = tid; l < BK * (BN / 4); l += NT) {
            int r = l / (BN / 4), c4 = l % (BN / 4);
            float4 v = *(const float4*)(B + (size_t)(k0 + r) * N + colBase + c4 * 4);
            Bs[c4 * 4 + 0][r] = __float2half_rn(v.x);
            Bs[c4 * 4 + 1][r] = __float2half_rn(v.y);
            Bs[c4 * 4 + 2][r] = __float2half_rn(v.z);
            Bs[c4 * 4 + 3][r] = __float2half_rn(v.w);
        }
        __syncthreads();

#pragma unroll
        for (int ks = 0; ks < BK; ks += 16) {
            uint32_t af[MF][4];
#pragma unroll
            for (int mf = 0; mf < MF; mf++) {
                int m0 = wm * WM + mf * 16;
                af[mf][0] = *(const uint32_t*)&As[m0 + g    ][ks + 2 * tg];
                af[mf][1] = *(const uint32_t*)&As[m0 + g + 8][ks + 2 * tg];
                af[mf][2] = *(const uint32_t*)&As[m0 + g    ][ks + 2 * tg + 8];
                af[mf][3] = *(const uint32_t*)&As[m0 + g + 8][ks + 2 * tg + 8];
            }
            uint32_t bf[NF][2];
#pragma unroll
            for (int nf = 0; nf < NF; nf++) {
                int n0 = wn * WN + nf * 8;
                bf[nf][0] = *(const uint32_t*)&Bs[n0 + g][ks + 2 * tg];
                bf[nf][1] = *(const uint32_t*)&Bs[n0 + g][ks + 2 * tg + 8];
            }
#pragma unroll
            for (int mf = 0; mf < MF; mf++)
#pragma unroll
                for (int nf = 0; nf < NF; nf++)
                    mma_f16(acc[mf][nf], af[mf], bf[nf]);
        }
        __syncthreads();
    }

    // ---- store C ----
#pragma unroll
    for (int mf = 0; mf < MF; mf++)
#pragma unroll
        for (int nf = 0; nf < NF; nf++) {
            int r0 = rowBase + wm * WM + mf * 16 + g;
            int r1 = r0 + 8;
            int col = colBase + wn * WN + nf * 8 + tg * 2;
            if (HALF_OUT) {
                __half* C = (__half*)Cv;
                if (r0 < M)
                    *(__half2*)&C[(size_t)r0 * N + col] =
                        __floats2half2_rn(acc[mf][nf][0], acc[mf][nf][1]);
                if (r1 < M)
                    *(__half2*)&C[(size_t)r1 * N + col] =
                        __floats2half2_rn(acc[mf][nf][2], acc[mf][nf][3]);
            } else {
                float* C = (float*)Cv;
                if (r0 < M)
                    *(float2*)&C[(size_t)r0 * N + col] =
                        make_float2(acc[mf][nf][0], acc[mf][nf][1]);
                if (r1 < M)
                    *(float2*)&C[(size_t)r1 * N + col] =
                        make_float2(acc[mf][nf][2], acc[mf][nf][3]);
            }
        }

    // ---- fused attention projection ----
    {
        constexpr int NH_W = WN / HEAD_W;
        constexpr int NFH  = HEAD_W / 8;
        constexpr int NHT  = N / HEAD_W;
#pragma unroll
        for (int mf = 0; mf < MF; mf++) {
            int r0 = rowBase + wm * WM + mf * 16 + g;
            int r1 = r0 + 8;
#pragma unroll
            for (int h = 0; h < NH_W; h++) {
                float e0 = 0.f, e1 = 0.f, f0 = 0.f, f1 = 0.f;
#pragma unroll
                for (int q = 0; q < NFH; q++) {
                    int nf = h * NFH + q;
                    int c = colBase + wn * WN + nf * 8 + tg * 2;
                    float a0 = al[c], a1 = al[c + 1];
                    float b0 = ar[c], b1 = ar[c + 1];
                    e0 += acc[mf][nf][0] * a0 + acc[mf][nf][1] * a1;
                    f0 += acc[mf][nf][0] * b0 + acc[mf][nf][1] * b1;
                    e1 += acc[mf][nf][2] * a0 + acc[mf][nf][3] * a1;
                    f1 += acc[mf][nf][2] * b0 + acc[mf][nf][3] * b1;
                }
                e0 += __shfl_xor_sync(0xffffffffu, e0, 1);
                e0 += __shfl_xor_sync(0xffffffffu, e0, 2);
                f0 += __shfl_xor_sync(0xffffffffu, f0, 1);
                f0 += __shfl_xor_sync(0xffffffffu, f0, 2);
                e1 += __shfl_xor_sync(0xffffffffu, e1, 1);
                e1 += __shfl_xor_sync(0xffffffffu, e1, 2);
                f1 += __shfl_xor_sync(0xffffffffu, f1, 1);
                f1 += __shfl_xor_sync(0xffffffffu, f1, 2);
                if (tg == 0) {
                    int head = (colBase + wn * WN) / HEAD_W + h;
                    if (r0 < M) { elo[r0 * NHT + head] = e0; ero[r0 * NHT + head] = f0; }
                    if (r1 < M) { elo[r1 * NHT + head] = e1; ero[r1 * NHT + head] = f1; }
                }
            }
        }
    }
}

// ================= layer-1 aggregate: warp per dst, x4 unroll, HFMA2 =============
// (R12 form — the best measured variant.) Batched alpha: lane L evaluates
// head L&7 for edge slot L>>3.
__global__ void agg1_csr_k(int N, const int* __restrict__ cnt, const int* __restrict__ csrc,
                           const float* __restrict__ el, const float* __restrict__ er,
                           const __half* __restrict__ z, const float* __restrict__ b,
                           __half* __restrict__ out) {
    int d = (blockIdx.x * blockDim.x + threadIdx.x) >> 5;
    int lane = threadIdx.x & 31;
    if (d >= N) return;
    int deg = cnt[d]; if (deg > BUCKET) deg = BUCKET;
    const int* row = csrc + (size_t)d * BUCKET;
    const int h8   = lane & 7;
    const int eidx = lane >> 3;
    const int hsel = lane >> 2;
    float erh = er[d * H1 + h8];

    float facc[8];
#pragma unroll
    for (int j = 0; j < 8; j++) facc[j] = 0.f;
    float denh = 0.f;

    const __half2 hz = __floats2half2_rn(0.f, 0.f);

    int i = 0;
    for (; i + 3 < deg; i += 4) {
        int4 ev = *(const int4*)&row[i];
        int s0 = ev.x, s1 = ev.y, s2 = ev.z, s3 = ev.w;
        int ss = (eidx == 0) ? s0 : (eidx == 1) ? s1 : (eidx == 2) ? s2 : s3;
        float ex = __expf(lrelu(el[ss * H1 + h8] + erh));
        denh += ex;
        __half2 a0 = __float2half2_rn(__shfl_sync(0xffffffffu, ex, hsel));
        __half2 a1 = __float2half2_rn(__shfl_sync(0xffffffffu, ex, 8  + hsel));
        __half2 a2 = __float2half2_rn(__shfl_sync(0xffffffffu, ex, 16 + hsel));
        __half2 a3 = __float2half2_rn(__shfl_sync(0xffffffffu, ex, 24 + hsel));
        uint4 v0 = ((const uint4*)(z + (size_t)s0 * C1))[lane];
        uint4 v1 = ((const uint4*)(z + (size_t)s1 * C1))[lane];
        uint4 v2 = ((const uint4*)(z + (size_t)s2 * C1))[lane];
        uint4 v3 = ((const uint4*)(z + (size_t)s3 * C1))[lane];
        __half2 h0 = hz, h1 = hz, h2 = hz, h3 = hz;
        h0 = __hfma2(*(__half2*)&v0.x, a0, h0);
        h1 = __hfma2(*(__half2*)&v0.y, a0, h1);
        h2 = __hfma2(*(__half2*)&v0.z, a0, h2);
        h3 = __hfma2(*(__half2*)&v0.w, a0, h3);
        h0 = __hfma2(*(__half2*)&v1.x, a1, h0);
        h1 = __hfma2(*(__half2*)&v1.y, a1, h1);
        h2 = __hfma2(*(__half2*)&v1.z, a1, h2);
        h3 = __hfma2(*(__half2*)&v1.w, a1, h3);
        h0 = __hfma2(*(__half2*)&v2.x, a2, h0);
        h1 = __hfma2(*(__half2*)&v2.y, a2, h1);
        h2 = __hfma2(*(__half2*)&v2.z, a2, h2);
        h3 = __hfma2(*(__half2*)&v2.w, a2, h3);
        h0 = __hfma2(*(__half2*)&v3.x, a3, h0);
        h1 = __hfma2(*(__half2*)&v3.y, a3, h1);
        h2 = __hfma2(*(__half2*)&v3.z, a3, h2);
        h3 = __hfma2(*(__half2*)&v3.w, a3, h3);
        float2 p;
        p = __half22float2(h0); facc[0] += p.x; facc[1] += p.y;
        p = __half22float2(h1); facc[2] += p.x; facc[3] += p.y;
        p = __half22float2(h2); facc[4] += p.x; facc[5] += p.y;
        p = __half22float2(h3); facc[6] += p.x; facc[7] += p.y;
    }
    for (; i < deg; i++) {              // tail: lanes 0-7 evaluate heads
        int s = row[i];
        float ex = 0.f;
        if (lane < H1) {
            ex = __expf(lrelu(el[s * H1 + lane] + erh));
            denh += ex;
        }
        float a = __shfl_sync(0xffffffffu, ex, hsel);
        uint4 v = ((const uint4*)(z + (size_t)s * C1))[lane];
        float2 p;
        p = __half22float2(*(__half2*)&v.x); facc[0] += a*p.x; facc[1] += a*p.y;
        p = __half22float2(*(__half2*)&v.y); facc[2] += a*p.x; facc[3] += a*p.y;
        p = __half22float2(*(__half2*)&v.z); facc[4] += a*p.x; facc[5] += a*p.y;
        p = __half22float2(*(__half2*)&v.w); facc[6] += a*p.x; facc[7] += a*p.y;
    }
    // fold per-lane partial denominators: lanes {h, h+8, h+16, h+24} hold head h
    denh += __shfl_xor_sync(0xffffffffu, denh, 8);
    denh += __shfl_xor_sync(0xffffffffu, denh, 16);
    float den = __shfl_sync(0xffffffffu, denh, hsel);
    float inv = den > 0.f ? 1.f / den : 0.f;

    int col = lane * 8;
    float4 b0 = *(const float4*)(b + col), b1 = *(const float4*)(b + col + 4);
    __half2 o0 = __floats2half2_rn(eluf(facc[0]*inv + b0.x), eluf(facc[1]*inv + b0.y));
    __half2 o1 = __floats2half2_rn(eluf(facc[2]*inv + b0.z), eluf(facc[3]*inv + b0.w));
    __half2 o2 = __floats2half2_rn(eluf(facc[4]*inv + b1.x), eluf(facc[5]*inv + b1.y));
    __half2 o3 = __floats2half2_rn(eluf(facc[6]*inv + b1.z), eluf(facc[7]*inv + b1.w));
    uint4 ov = make_uint4(*(uint32_t*)&o0, *(uint32_t*)&o1,
                          *(uint32_t*)&o2, *(uint32_t*)&o3);
    ((uint4*)(out + (size_t)d * C1))[lane] = ov;
}

// ================= layer-2 aggregate: warp per dst, fp16 z2, 2 edges x2 unroll ===
__global__ void agg2_csr_k(int N, const int* __restrict__ cnt, const int* __restrict__ csrc,
                           const float* __restrict__ el, const float* __restrict__ er,
                           const __half* __restrict__ z, const float* __restrict__ b,
                           float* __restrict__ out) {
    int d = (blockIdx.x * blockDim.x + threadIdx.x) >> 5;
    int lane = threadIdx.x & 31;
    if (d >= N) return;
    int deg = cnt[d]; if (deg > BUCKET) deg = BUCKET;
    const int* row = csrc + (size_t)d * BUCKET;
    int half = lane >> 4, hl = lane & 15;
    float erd = er[d];
    float4 acc = make_float4(0.f, 0.f, 0.f, 0.f);
    float den = 0.f;
    int i = half;
    for (; i + 2 < deg; i += 4) {       // two independent edges per half-warp
        int sa = row[i], sb = row[i + 2];
        float exa = __expf(lrelu(el[sa] + erd));
        float exb = __expf(lrelu(el[sb] + erd));
        den += exa + exb;
        if (hl < OUTD / 4) {
            uint2 va = ((const uint2*)(z + (size_t)sa * OUTD))[hl];
            uint2 vb = ((const uint2*)(z + (size_t)sb * OUTD))[hl];
            float2 p0 = __half22float2(*(__half2*)&va.x);
            float2 p1 = __half22float2(*(__half2*)&va.y);
            float2 q0 = __half22float2(*(__half2*)&vb.x);
            float2 q1 = __half22float2(*(__half2*)&vb.y);
            acc.x += exa * p0.x + exb * q0.x;
            acc.y += exa * p0.y + exb * q0.y;
            acc.z += exa * p1.x + exb * q1.x;
            acc.w += exa * p1.y + exb * q1.y;
        }
    }
    for (; i < deg; i += 2) {
        int s = row[i];
        float ex = __expf(lrelu(el[s] + erd));
        den += ex;
        if (hl < OUTD / 4) {
            uint2 v = ((const uint2*)(z + (size_t)s * OUTD))[hl];
            float2 p0 = __half22float2(*(__half2*)&v.x);
            float2 p1 = __half22float2(*(__half2*)&v.y);
            acc.x += ex * p0.x; acc.y += ex * p0.y;
            acc.z += ex * p1.x; acc.w += ex * p1.y;
        }
    }
    acc.x += __shfl_down_sync(0xffffffffu, acc.x, 16);
    acc.y += __shfl_down_sync(0xffffffffu, acc.y, 16);
    acc.z += __shfl_down_sync(0xffffffffu, acc.z, 16);
    acc.w += __shfl_down_sync(0xffffffffu, acc.w, 16);
    den   += __shfl_down_sync(0xffffffffu, den, 16);
    float inv = den > 0.f ? 1.f / den : 0.f;
    if (lane < OUTD / 4) {
        float4 bv = ((const float4*)b)[lane];
        float4 o;
        o.x = acc.x * inv + bv.x; o.y = acc.y * inv + bv.y;
        o.z = acc.z * inv + bv.z; o.w = acc.w * inv + bv.w;
        ((float4*)(out + (size_t)d * OUTD))[lane] = o;
    }
}

// ---------------- stream/event resources (static-init; serial fallback) ----------
struct SideStream {
    cudaStream_t s = nullptr;
    cudaEvent_t  fork = nullptr, join = nullptr;
    bool ok = false;
    SideStream() {
        ok = (cudaStreamCreateWithFlags(&s, cudaStreamNonBlocking) == cudaSuccess)
          && (cudaEventCreateWithFlags(&fork, cudaEventDisableTiming) == cudaSuccess)
          && (cudaEventCreateWithFlags(&join, cudaEventDisableTiming) == cudaSuccess);
    }
};
static SideStream g_ss;

// ---------------- launch ----------------
static inline int cdiv(int a, int b) { return (a + b - 1) / b; }

extern "C" void kernel_launch(void* const* d_in, const int* in_sizes, int n_in,
                              void* d_out, int out_size) {
    const float* feat = (const float*)d_in[0];
    const int*   src  = (const int*)  d_in[1];
    const int*   dst  = (const int*)  d_in[2];
    const float* W1   = (const float*)d_in[3];
    const float* al1  = (const float*)d_in[4];
    const float* ar1  = (const float*)d_in[5];
    const float* b1   = (const float*)d_in[6];
    const float* W2   = (const float*)d_in[7];
    const float* al2  = (const float*)d_in[8];
    const float* ar2  = (const float*)d_in[9];
    const float* b2   = (const float*)d_in[10];
    float* out = (float*)d_out;

    const int N = in_sizes[0] / INSZ;
    const int E = in_sizes[1];

    __half *z1h, *h1h, *z2h;
    float *el1, *er1, *el2, *er2;
    int *cnt, *csrc;
    cudaGetSymbolAddress((void**)&z1h,  g_z1h);
    cudaGetSymbolAddress((void**)&h1h,  g_h1h);
    cudaGetSymbolAddress((void**)&el1,  g_el1);
    cudaGetSymbolAddress((void**)&er1,  g_er1);
    cudaGetSymbolAddress((void**)&z2h,  g_z2h);
    cudaGetSymbolAddress((void**)&el2,  g_el2);
    cudaGetSymbolAddress((void**)&er2,  g_er2);
    cudaGetSymbolAddress((void**)&cnt,  g_cnt);
    cudaGetSymbolAddress((void**)&csrc, g_csrc);

    const int T = 256;
    const int TA = 128;
    const bool forked = g_ss.ok;
    cudaStream_t sc = forked ? g_ss.s : (cudaStream_t)0;

    if (forked) {
        cudaEventRecord(g_ss.fork, 0);
        cudaStreamWaitEvent(sc, g_ss.fork, 0);
    }

    // ---- bucket-CSR build (side stream; shared by both layers) ----
    zero1_k  <<<cdiv(N, T), T, 0, sc>>>(N, cnt);
    scatter_k<<<cdiv(E, T), T, 0, sc>>>(E, src, dst, cnt, csrc);
    if (forked) cudaEventRecord(g_ss.join, sc);

    // ---- layer 1: GEMM + fused attn projection ----
    {
        dim3 grid(C1 / 128, cdiv(N, 128));
        h16gemm_k<C1, INSZ, 128, 128, 32, 4, 2, 256, false, true, HID>
            <<<grid, 256>>>(N, (const void*)feat, W1, (void*)z1h, al1, ar1, el1, er1);
    }

    if (forked) cudaStreamWaitEvent(0, g_ss.join, 0);

    agg1_csr_k<<<cdiv(N * 32, TA), TA>>>(N, cnt, csrc, el1, er1, z1h, b1, h1h);

    // ---- layer 2: GEMM (256 threads, WARPS_M=8) + fused attn projection ----
    {
        dim3 grid(1, cdiv(N, 128));
        h16gemm_k<OUTD, C1, 128, 40, 32, 8, 1, 256, true, true, OUTD>
            <<<grid, 256>>>(N, (const void*)h1h, W2, (void*)z2h, al2, ar2, el2, er2);
    }
    agg2_csr_k<<<cdiv(N * 32, TA), TA>>>(N, cnt, csrc, el2, er2, z2h, b2, out);
}